// round 11
// baseline (speedup 1.0000x reference)
#include <cuda_runtime.h>
#include <cstdint>

#define BB 16
#define VV 8
#define SS 256
#define KK 66
#define NSEQ 128                 // B*V
#define CRF_BLOCKS 128
#define AM_BLOCKS 592
#define THREADS 128
#define ROWS (BB*SS*SS)          // 1,048,576 argmax rows
#define RPI 8                    // rows per inner iteration (argmax)
#define CHUNK_ROWS 128
#define NCHUNK (ROWS / CHUNK_ROWS)   // 8192

__device__ float g_part[NSEQ];
__device__ unsigned int g_cnt;    // CRF completion counter (zero-init)
__device__ unsigned int g_amcnt;  // argmax work-steal counter (zero-init)

__device__ __forceinline__ void ffma2(unsigned long long& d,
                                      unsigned long long a,
                                      unsigned long long b)
{
    asm("fma.rn.f32x2 %0, %1, %2, %0;" : "+l"(d) : "l"(a), "l"(b));
}

__global__ void __launch_bounds__(THREADS, 4) fused_kernel(
    const float* __restrict__ lp,          // log_pa (B,S,S,K)
    const float* __restrict__ score,       // (B,S,S,K)
    const int*   __restrict__ v_label,     // (B,V)
    const int*   __restrict__ orig_l,      // (B,)
    const int*   __restrict__ role_label,  // (B,V,S)
    const float* __restrict__ start_t,     // (K,)
    const float* __restrict__ trans,       // (K,K)
    const float* __restrict__ end_t,       // (K,)
    float* __restrict__ out)               // [0]=loss, [1..]=pred_idx
{
    const int tid  = threadIdx.x;
    const int lane = tid & 31;

    if (blockIdx.x >= CRF_BLOCKS) {
        // ============================ argmax path ============================
        // Warp-level dynamic work stealing; two-phase (batched) loads.
        const unsigned FULL = 0xffffffffu;
        for (;;) {
            unsigned c;
            if (lane == 0) c = atomicAdd(&g_amcnt, 1u);
            c = __shfl_sync(FULL, c, 0);
            if (c >= NCHUNK) break;
            const int cbase = (int)c * CHUNK_ROWS;
#pragma unroll 1
            for (int it = 0; it < CHUNK_ROWS / RPI; ++it) {
                const int base = cbase + it * RPI;
                float v0[RPI], v1[RPI], v2[RPI];
#pragma unroll
                for (int r = 0; r < RPI; ++r) {
                    const float* p = lp + (size_t)(base + r) * KK + lane;
                    v0[r] = __ldg(p);
                    v1[r] = __ldg(p + 32);
                    v2[r] = (lane < 2) ? __ldg(p + 64) : -3.402823466e38f;
                }
#pragma unroll
                for (int r = 0; r < RPI; ++r) {
                    float best = v0[r]; int bi = lane;
                    if (v1[r] > best) { best = v1[r]; bi = lane + 32; }
                    if (v2[r] > best) { best = v2[r]; bi = lane + 64; }
                    unsigned kb = __float_as_uint(best);
                    kb = (kb & 0x80000000u) ? ~kb : (kb | 0x80000000u);
                    unsigned kmax = __reduce_max_sync(FULL, kb);
                    unsigned cand = (kb == kmax) ? (unsigned)bi : 0xffffffffu;
                    unsigned imin = __reduce_min_sync(FULL, cand);
                    if (lane == 0) out[1 + base + r] = (float)imin;
                }
            }
        }
        return;
    }

    // =============================== CRF path ===============================
    __shared__ float sRing[16][KK];         // prefetched exp(score) rows
    __shared__ __align__(16) float sA[2][72];
    __shared__ int   sTag[SS];
    __shared__ float sRed[THREADS];
    __shared__ float sScale[2];             // [0]=1/m, [1]=log(m)
    __shared__ int   sLast;

    const int n = blockIdx.x;
    const int b = n >> 3;                   // / VV
    const int qrow = v_label[n];
    const int L = orig_l[b];                // >= S/2 >= 2
    const float* asc = score + ((size_t)b * SS + qrow) * SS * KK;

    // tags + alpha pad init
    for (int t = tid; t < L; t += THREADS) sTag[t] = role_label[(size_t)n * SS + t];
    if (tid < 6) { sA[0][66 + tid] = 0.f; sA[1][66 + tid] = 0.f; }
    __syncthreads();

    // initial ring fill: rows 0..15
    for (int idx = tid; idx < 16 * KK; idx += THREADS) {
        int t = idx / KK, j = idx - t * KK;
        sRing[t][j] = __expf(__ldg(asc + t * KK + j));
    }

    // numerator: emission + transition gold path
    float acc = 0.f;
    for (int t = tid; t < L; t += THREADS)
        acc += __ldg(asc + t * KK + sTag[t]);
    for (int t = tid + 1; t < L; t += THREADS)
        acc += __ldg(trans + sTag[t - 1] * KK + sTag[t]);
    sRed[tid] = acc;

    // packed exp(trans) column: T2[p] = (exp(T[2p][j]), exp(T[2p+1][j]))
    unsigned long long T2[34];
    if (tid < 66) {
#pragma unroll
        for (int p = 0; p < 33; ++p) {
            float lo = __expf(__ldg(trans + (2 * p)     * KK + tid));
            float hi = __expf(__ldg(trans + (2 * p + 1) * KK + tid));
            asm("mov.b64 %0, {%1, %2};" : "=l"(T2[p]) : "f"(lo), "f"(hi));
        }
        {
            float lo = 0.f, hi = 0.f;  // rows 66,67 are padding
            asm("mov.b64 %0, {%1, %2};" : "=l"(T2[33]) : "f"(lo), "f"(hi));
        }
    } else {
#pragma unroll
        for (int p = 0; p < 34; ++p) T2[p] = 0ull;
    }

    __syncthreads();
    for (int s = 64; s > 0; s >>= 1) {      // deterministic tree reduce
        if (tid < s) sRed[tid] += sRed[tid + s];
        __syncthreads();
    }
    float numer = 0.f;
    if (tid == 0)
        numer = sRed[0] + __ldg(start_t + sTag[0]) + __ldg(end_t + sTag[L - 1]);

    // alpha0 (exp domain): A[j] = exp(start_t[j]) * E[0][j]
    if (tid < 66) sA[0][tid] = __expf(start_t[tid]) * sRing[0][tid];
    __syncthreads();

    float* Ac = sA[0];
    float* An = sA[1];
    float Cl = 0.f;
    for (int t = 1; t < L; ++t) {
        float inv = 1.f;
        if ((t & 3) == 0) {                 // renormalize every 4 steps
            if (tid < 32) {
                float m = fmaxf(Ac[tid], Ac[tid + 32]);
                if (tid < 2) m = fmaxf(m, Ac[tid + 64]);
#pragma unroll
                for (int off = 16; off > 0; off >>= 1)
                    m = fmaxf(m, __shfl_down_sync(0xffffffffu, m, off));
                if (tid == 0) { sScale[0] = 1.f / m; sScale[1] = __logf(m); }
            }
            __syncthreads();
            inv = sScale[0];
            Cl += sScale[1];
        }
        if (tid < 66) {
            // batch all alpha loads before the FMA chain
            const ulonglong2* A2 = (const ulonglong2*)Ac;
            unsigned long long q0[17], q1[17];
#pragma unroll
            for (int ii = 0; ii < 17; ++ii) { ulonglong2 v = A2[ii]; q0[ii] = v.x; q1[ii] = v.y; }
            unsigned long long acc0 = 0ull, acc1 = 0ull;  // packed (0.f, 0.f)
#pragma unroll
            for (int ii = 0; ii < 17; ++ii) {
                ffma2(acc0, q0[ii], T2[2 * ii]);
                ffma2(acc1, q1[ii], T2[2 * ii + 1]);
            }
            float f0, f1, f2, f3;
            asm("mov.b64 {%0, %1}, %2;" : "=f"(f0), "=f"(f1) : "l"(acc0));
            asm("mov.b64 {%0, %1}, %2;" : "=f"(f2), "=f"(f3) : "l"(acc1));
            float s = (f0 + f2) + (f1 + f3);
            An[tid] = s * inv * sRing[t & 15][tid];
        } else if (tid >= 96) {
            // warp 3: prefetch exp(score) row t+15 into ring slot (t-1)&15
            const int tl = t + 15;
            if (tl < SS) {
                const int j = tid - 96;     // 0..31
                const float* p = asc + tl * KK;
                float* dst = sRing[tl & 15];
                dst[j]      = __expf(__ldg(p + j));
                dst[j + 32] = __expf(__ldg(p + j + 32));
                if (j < 2) dst[j + 64] = __expf(__ldg(p + j + 64));
            }
        }
        __syncthreads();
        float* tmp = Ac; Ac = An; An = tmp;
    }

    // log_z = Cl + log( sum_j A[j] * exp(end_t[j]) )
    float val = 0.f;
    if (tid < 66) val = Ac[tid] * __expf(end_t[tid]);
    sRed[tid] = val;
    __syncthreads();
    for (int s = 64; s > 0; s >>= 1) {
        if (tid < s) sRed[tid] += sRed[tid + s];
        __syncthreads();
    }
    if (tid == 0) {
        float logz = Cl + __logf(sRed[0]);
        g_part[n] = numer - logz;
    }

    // last CRF block finalizes the loss
    __threadfence();
    if (tid == 0) {
        unsigned done = atomicAdd(&g_cnt, 1u);
        sLast = (done == NSEQ - 1);
    }
    __syncthreads();
    if (sLast) {
        __threadfence();
        sRed[tid] = g_part[tid];
        __syncthreads();
        for (int s = 64; s > 0; s >>= 1) {
            if (tid < s) sRed[tid] += sRed[tid + s];
            __syncthreads();
        }
        if (tid == 0) out[0] = sRed[0] / (float)NSEQ;
    }
}

// zero the counters so graph replays start clean
__global__ void reset_kernel()
{
    if (threadIdx.x == 0) { g_cnt = 0u; g_amcnt = 0u; }
}

extern "C" void kernel_launch(void* const* d_in, const int* in_sizes, int n_in,
                              void* d_out, int out_size)
{
    (void)in_sizes; (void)n_in; (void)out_size;
    const float* log_pa     = (const float*)d_in[0];
    const float* score      = (const float*)d_in[1];
    const int*   v_label    = (const int*)d_in[2];
    // d_in[3] = v_l (unused by reference)
    const int*   orig_l     = (const int*)d_in[4];
    const int*   role_label = (const int*)d_in[5];
    const float* start_t    = (const float*)d_in[6];
    const float* trans      = (const float*)d_in[7];
    const float* end_t      = (const float*)d_in[8];
    float* out = (float*)d_out;

    fused_kernel<<<CRF_BLOCKS + AM_BLOCKS, THREADS>>>(
        log_pa, score, v_label, orig_l, role_label, start_t, trans, end_t, out);
    reset_kernel<<<1, 32>>>();
}

// round 12
// speedup vs baseline: 1.0265x; 1.0265x over previous
#include <cuda_runtime.h>
#include <cstdint>

#define BB 16
#define VV 8
#define SS 256
#define KK 66
#define KP 68                    // padded row pitch for float4
#define NSEQ 128                 // B*V
#define CRF_BLOCKS 128
#define AM_BLOCKS 1920
#define THREADS 256
#define ROWS (BB*SS*SS)          // 1,048,576 argmax rows
#define RPI 4                    // rows per warp-iteration (argmax)

__device__ float g_part[NSEQ];
__device__ unsigned int g_cnt;   // zero-init; self-resets each launch

__global__ void __launch_bounds__(THREADS, 4) fused_kernel(
    const float* __restrict__ lp,          // log_pa (B,S,S,K)
    const float* __restrict__ score,       // (B,S,S,K)
    const int*   __restrict__ v_label,     // (B,V)
    const int*   __restrict__ orig_l,      // (B,)
    const int*   __restrict__ role_label,  // (B,V,S)
    const float* __restrict__ start_t,     // (K,)
    const float* __restrict__ trans,       // (K,K)
    const float* __restrict__ end_t,       // (K,)
    float* __restrict__ out)               // [0]=loss, [1..]=pred_idx
{
    const int tid  = threadIdx.x;
    const int lane = tid & 31;

    if (blockIdx.x >= CRF_BLOCKS) {
        // ============================ argmax path ============================
        // Grid-stride, two-phase (batched) loads, first-occurrence tie-break.
        const unsigned FULL = 0xffffffffu;
        const int gw = (int)(blockIdx.x - CRF_BLOCKS) * (THREADS / 32) + (tid >> 5);
        const int nw = AM_BLOCKS * (THREADS / 32);

        for (int base = gw * RPI; base < ROWS; base += nw * RPI) {
            float v0[RPI], v1[RPI], v2[RPI];
#pragma unroll
            for (int r = 0; r < RPI; ++r) {
                const float* p = lp + (size_t)(base + r) * KK + lane;
                v0[r] = __ldg(p);
                v1[r] = __ldg(p + 32);
                v2[r] = (lane < 2) ? __ldg(p + 64) : -3.402823466e38f;
            }
#pragma unroll
            for (int r = 0; r < RPI; ++r) {
                float best = v0[r]; int bi = lane;
                if (v1[r] > best) { best = v1[r]; bi = lane + 32; }
                if (v2[r] > best) { best = v2[r]; bi = lane + 64; }
                unsigned kb = __float_as_uint(best);
                kb = (kb & 0x80000000u) ? ~kb : (kb | 0x80000000u);
                unsigned kmax = __reduce_max_sync(FULL, kb);
                unsigned cand = (kb == kmax) ? (unsigned)bi : 0xffffffffu;
                unsigned imin = __reduce_min_sync(FULL, cand);
                if (lane == 0) out[1 + base + r] = (float)imin;
            }
        }
        return;
    }

    // =============================== CRF path ===============================
    __shared__ __align__(16) float sTt[KK][KP];   // sTt[j][i] = exp(trans[i][j])
    __shared__ __align__(16) float sRing[16][KK]; // prefetched exp(score) rows
    __shared__ __align__(16) float sA[2][72];
    __shared__ int   sTag[SS];
    __shared__ float sRed[THREADS];
    __shared__ float sScale[2];                   // [0]=1/m, [1]=log(m)
    __shared__ int   sLast;

    const int n = blockIdx.x;
    const int b = n >> 3;                   // / VV
    const int qrow = v_label[n];
    const int L = orig_l[b];                // >= S/2 >= 2
    const float* asc = score + ((size_t)b * SS + qrow) * SS * KK;

    // tags + alpha pad init + Tt pad init
    for (int t = tid; t < L; t += THREADS) sTag[t] = role_label[(size_t)n * SS + t];
    if (tid < 6) { sA[0][66 + tid] = 0.f; sA[1][66 + tid] = 0.f; }
    for (int idx = tid; idx < KK * 2; idx += THREADS)
        sTt[idx >> 1][66 + (idx & 1)] = 0.f;

    // transposed exp(trans) into smem
    for (int idx = tid; idx < KK * KK; idx += THREADS) {
        int i = idx / KK, j = idx - i * KK;
        sTt[j][i] = __expf(__ldg(trans + idx));
    }

    // initial ring fill: rows 0..15
    for (int idx = tid; idx < 16 * KK; idx += THREADS) {
        int t = idx / KK, j = idx - t * KK;
        sRing[t][j] = __expf(__ldg(asc + t * KK + j));
    }

    // numerator: emission + transition gold path
    float acc = 0.f;
    for (int t = tid; t < L; t += THREADS)
        acc += __ldg(asc + t * KK + sTag[t]);
    __syncthreads();            // sTag visible (also covers Tt/ring before use)
    for (int t = tid + 1; t < L; t += THREADS)
        acc += __ldg(trans + sTag[t - 1] * KK + sTag[t]);
    sRed[tid] = acc;
    __syncthreads();
    for (int s = 128; s > 0; s >>= 1) {     // deterministic tree reduce
        if (tid < s) sRed[tid] += sRed[tid + s];
        __syncthreads();
    }
    float numer = 0.f;
    if (tid == 0)
        numer = sRed[0] + __ldg(start_t + sTag[0]) + __ldg(end_t + sTag[L - 1]);

    // alpha0 (exp domain): A[j] = exp(start_t[j]) * E[0][j]
    if (tid < 66) sA[0][tid] = __expf(start_t[tid]) * sRing[0][tid];
    __syncthreads();

    float* Ac = sA[0];
    float* An = sA[1];
    float Cl = 0.f;
    for (int t = 1; t < L; ++t) {
        float inv = 1.f;
        if ((t & 3) == 0) {                 // renormalize every 4 steps
            if (tid < 32) {
                float m = fmaxf(Ac[tid], Ac[tid + 32]);
                if (tid < 2) m = fmaxf(m, Ac[tid + 64]);
#pragma unroll
                for (int off = 16; off > 0; off >>= 1)
                    m = fmaxf(m, __shfl_down_sync(0xffffffffu, m, off));
                if (tid == 0) { sScale[0] = 1.f / m; sScale[1] = __logf(m); }
            }
            __syncthreads();
            inv = sScale[0];
            Cl += sScale[1];
        }
        if (tid < 66) {
            // new[j] = E[t][j] * sum_i A[i] * Texp[i][j]
            const float4* Trow = (const float4*)&sTt[tid][0];  // private row
            const float4* A4   = (const float4*)Ac;            // broadcast
            float a0 = 0.f, a1 = 0.f, a2 = 0.f, a3 = 0.f;
#pragma unroll
            for (int ii = 0; ii < 17; ++ii) {
                float4 tv = Trow[ii];
                float4 av = A4[ii];
                a0 = fmaf(av.x, tv.x, a0);
                a1 = fmaf(av.y, tv.y, a1);
                a2 = fmaf(av.z, tv.z, a2);
                a3 = fmaf(av.w, tv.w, a3);
            }
            float s = (a0 + a1) + (a2 + a3);
            An[tid] = s * inv * sRing[t & 15][tid];
        } else if (tid >= 128 && tid < 194) {
            // threads 128..193: prefetch exp(score) row t+15 into the freed slot
            const int tl = t + 15;
            if (tl < SS) {
                const int j = tid - 128;    // 0..65
                sRing[tl & 15][j] = __expf(__ldg(asc + tl * KK + j));
            }
        }
        __syncthreads();
        float* tmp = Ac; Ac = An; An = tmp;
    }

    // log_z = Cl + log( sum_j A[j] * exp(end_t[j]) )
    float val = 0.f;
    if (tid < 66) val = Ac[tid] * __expf(end_t[tid]);
    sRed[tid] = val;
    __syncthreads();
    for (int s = 128; s > 0; s >>= 1) {
        if (tid < s) sRed[tid] += sRed[tid + s];
        __syncthreads();
    }
    if (tid == 0) {
        float logz = Cl + __logf(sRed[0]);
        g_part[n] = numer - logz;
    }

    // last CRF block finalizes the loss (and self-resets the counter)
    __threadfence();
    if (tid == 0) {
        unsigned done = atomicAdd(&g_cnt, 1u);
        sLast = (done == NSEQ - 1);
    }
    __syncthreads();
    if (sLast) {
        __threadfence();
        sRed[tid] = (tid < NSEQ) ? g_part[tid] : 0.f;
        __syncthreads();
        for (int s = 128; s > 0; s >>= 1) {
            if (tid < s) sRed[tid] += sRed[tid + s];
            __syncthreads();
        }
        if (tid == 0) {
            out[0] = sRed[0] / (float)NSEQ;
            g_cnt = 0u;                      // all 128 increments already landed
            __threadfence();
        }
    }
}

extern "C" void kernel_launch(void* const* d_in, const int* in_sizes, int n_in,
                              void* d_out, int out_size)
{
    (void)in_sizes; (void)n_in; (void)out_size;
    const float* log_pa     = (const float*)d_in[0];
    const float* score      = (const float*)d_in[1];
    const int*   v_label    = (const int*)d_in[2];
    // d_in[3] = v_l (unused by reference)
    const int*   orig_l     = (const int*)d_in[4];
    const int*   role_label = (const int*)d_in[5];
    const float* start_t    = (const float*)d_in[6];
    const float* trans      = (const float*)d_in[7];
    const float* end_t      = (const float*)d_in[8];
    float* out = (float*)d_out;

    fused_kernel<<<CRF_BLOCKS + AM_BLOCKS, THREADS>>>(
        log_pa, score, v_label, orig_l, role_label, start_t, trans, end_t, out);
}